// round 1
// baseline (speedup 1.0000x reference)
#include <cuda_runtime.h>
#include <math.h>

#define BATCH 8
#define SEQ   2048
#define DIM   128
#define BM    64
#define BN    64
#define NQT   (SEQ / BM)   // 32 query tiles

// Scratch for projected Q, K, V (device globals — no allocation allowed)
__device__ float g_q[BATCH * SEQ * DIM];
__device__ float g_k[BATCH * SEQ * DIM];
__device__ float g_v[BATCH * SEQ * DIM];

// ---------------------------------------------------------------------------
// QKV projection: out[b,t,d] = sum_c x[b,t,c] * W[d,c]
// grid (NQT, BATCH, 3), block 256. SMEM: W transposed [c][d] + x tile [64][128]
// ---------------------------------------------------------------------------
__global__ __launch_bounds__(256, 1)
void qkv_kernel(const float* __restrict__ x,
                const float* __restrict__ Wk,
                const float* __restrict__ Wq,
                const float* __restrict__ Wv) {
    extern __shared__ float sm[];
    float* sWt = sm;               // [DIM][DIM] : sWt[c*DIM + d]
    float* sX  = sm + DIM * DIM;   // [BM][DIM]

    const int tq    = blockIdx.x;
    const int b     = blockIdx.y;
    const int which = blockIdx.z;
    const float* W  = (which == 0) ? Wq : (which == 1) ? Wk : Wv;
    float* out      = (which == 0) ? g_q : (which == 1) ? g_k : g_v;
    const int tid = threadIdx.x;

    // Load W transposed into SMEM
    {
        int d  = tid >> 1;
        int c0 = (tid & 1) * 64;
        const float4* src = (const float4*)(W + d * DIM + c0);
        #pragma unroll
        for (int i = 0; i < 16; i++) {
            float4 w = src[i];
            int c = c0 + i * 4;
            sWt[(c + 0) * DIM + d] = w.x;
            sWt[(c + 1) * DIM + d] = w.y;
            sWt[(c + 2) * DIM + d] = w.z;
            sWt[(c + 3) * DIM + d] = w.w;
        }
    }
    // Load x tile [64][128]
    {
        const float4* src = (const float4*)(x + ((size_t)b * SEQ + tq * BM) * DIM);
        float4* dst = (float4*)sX;
        #pragma unroll
        for (int i = 0; i < 8; i++)
            dst[tid + i * 256] = src[tid + i * 256];
    }
    __syncthreads();

    const int cx = tid & 31;   // 4 output cols: d = 4*cx ..
    const int ry = tid >> 5;   // 8 output rows: r = ry*8 ..
    float acc[8][4];
    #pragma unroll
    for (int i = 0; i < 8; i++)
        #pragma unroll
        for (int j = 0; j < 4; j++) acc[i][j] = 0.f;

    #pragma unroll 4
    for (int c = 0; c < DIM; c++) {
        float4 w = *(const float4*)(sWt + c * DIM + cx * 4);
        #pragma unroll
        for (int i = 0; i < 8; i++) {
            float xv = sX[(ry * 8 + i) * DIM + c];
            acc[i][0] += xv * w.x;
            acc[i][1] += xv * w.y;
            acc[i][2] += xv * w.z;
            acc[i][3] += xv * w.w;
        }
    }

    float* obase = out + ((size_t)b * SEQ + tq * BM) * DIM;
    #pragma unroll
    for (int i = 0; i < 8; i++) {
        float4 o = make_float4(acc[i][0], acc[i][1], acc[i][2], acc[i][3]);
        *(float4*)(obase + (ry * 8 + i) * DIM + cx * 4) = o;
    }
}

// ---------------------------------------------------------------------------
// Flash attention (causal, fp32). 1D grid of NQT*BATCH blocks, 256 threads.
// Heavy query tiles scheduled first for load balance.
// ---------------------------------------------------------------------------
__global__ __launch_bounds__(256, 1)
void attn_kernel(float* __restrict__ out) {
    extern __shared__ float sm[];
    float* sQ   = sm;                    // [64][128]
    float* sKt  = sQ  + BM * DIM;        // [128][64] : sKt[d*BN + c]
    float* sV   = sKt + DIM * BN;        // [64][128]
    float* sS   = sV  + BN * DIM;        // [64][64]
    float* sM   = sS  + BM * BN;         // row max
    float* sL   = sM  + BM;              // row sum
    float* sA   = sL  + BM;              // rescale alpha
    float* pmax = sA  + BM;              // [64][4]
    float* psum = pmax + BM * 4;         // [64][4]

    const int bid = blockIdx.x;
    const int qt  = (NQT - 1) - (bid >> 3);   // heavy tiles first
    const int b   = bid & 7;
    const int tid = threadIdx.x;
    const int qbase = qt * BM;

    const float* Q = g_q + ((size_t)b * SEQ + qbase) * DIM;
    const float* K = g_k + (size_t)b * SEQ * DIM;
    const float* V = g_v + (size_t)b * SEQ * DIM;

    // Load Q tile, pre-scaled by 1/sqrt(DIM)
    const float scale = 0.08838834764831845f;
    {
        const float4* src = (const float4*)Q;
        float4* dst = (float4*)sQ;
        #pragma unroll
        for (int i = 0; i < 8; i++) {
            float4 v = src[tid + i * 256];
            v.x *= scale; v.y *= scale; v.z *= scale; v.w *= scale;
            dst[tid + i * 256] = v;
        }
    }
    if (tid < BM) { sM[tid] = -1e30f; sL[tid] = 0.f; }

    float acc[8][4];
    #pragma unroll
    for (int i = 0; i < 8; i++)
        #pragma unroll
        for (int j = 0; j < 4; j++) acc[i][j] = 0.f;

    const int cx  = tid & 31;   // PV/output: 4 cols (d)
    const int ry  = tid >> 5;   // PV/output: 8 rows
    const int txS = tid & 15;   // S: 4 key cols
    const int tyS = tid >> 4;   // S: 4 query rows

    const int ntiles = qt + 1;
    for (int kt = 0; kt < ntiles; kt++) {
        __syncthreads();  // protect sKt/sV/sS reuse

        // Load K tile transposed + V tile
        {
            int c  = tid >> 2;
            int d0 = (tid & 3) * 32;
            const float4* ksrc = (const float4*)(K + ((size_t)(kt * BN + c)) * DIM + d0);
            #pragma unroll
            for (int i = 0; i < 8; i++) {
                float4 kv = ksrc[i];
                int d = d0 + i * 4;
                sKt[(d + 0) * BN + c] = kv.x;
                sKt[(d + 1) * BN + c] = kv.y;
                sKt[(d + 2) * BN + c] = kv.z;
                sKt[(d + 3) * BN + c] = kv.w;
            }
            const float4* vsrc = (const float4*)(V + (size_t)kt * BN * DIM);
            float4* vdst = (float4*)sV;
            #pragma unroll
            for (int i = 0; i < 8; i++)
                vdst[tid + i * 256] = vsrc[tid + i * 256];
        }
        __syncthreads();

        // S = Q @ K^T (each thread: 4x4 tile)
        float s[4][4];
        #pragma unroll
        for (int i = 0; i < 4; i++)
            #pragma unroll
            for (int j = 0; j < 4; j++) s[i][j] = 0.f;

        #pragma unroll 4
        for (int d = 0; d < DIM; d++) {
            float4 kk = *(const float4*)(sKt + d * BN + txS * 4);
            float q0 = sQ[(tyS * 4 + 0) * DIM + d];
            float q1 = sQ[(tyS * 4 + 1) * DIM + d];
            float q2 = sQ[(tyS * 4 + 2) * DIM + d];
            float q3 = sQ[(tyS * 4 + 3) * DIM + d];
            s[0][0] += q0 * kk.x; s[0][1] += q0 * kk.y; s[0][2] += q0 * kk.z; s[0][3] += q0 * kk.w;
            s[1][0] += q1 * kk.x; s[1][1] += q1 * kk.y; s[1][2] += q1 * kk.z; s[1][3] += q1 * kk.w;
            s[2][0] += q2 * kk.x; s[2][1] += q2 * kk.y; s[2][2] += q2 * kk.z; s[2][3] += q2 * kk.w;
            s[3][0] += q3 * kk.x; s[3][1] += q3 * kk.y; s[3][2] += q3 * kk.z; s[3][3] += q3 * kk.w;
        }

        // Causal mask on the diagonal tile
        if (kt == qt) {
            #pragma unroll
            for (int i = 0; i < 4; i++)
                #pragma unroll
                for (int j = 0; j < 4; j++)
                    if (txS * 4 + j > tyS * 4 + i) s[i][j] = -1e30f;
        }

        #pragma unroll
        for (int i = 0; i < 4; i++)
            *(float4*)(sS + (tyS * 4 + i) * BN + txS * 4) =
                make_float4(s[i][0], s[i][1], s[i][2], s[i][3]);
        __syncthreads();

        // Pass A: partial row max
        {
            int r = tid >> 2, p = tid & 3;
            const float* row = sS + r * BN + p * 16;
            float m = -1e30f;
            #pragma unroll
            for (int c = 0; c < 16; c++) m = fmaxf(m, row[c]);
            pmax[r * 4 + p] = m;
        }
        __syncthreads();
        if (tid < BM) {
            float mold = sM[tid];
            float mnew = fmaxf(fmaxf(pmax[tid * 4 + 0], pmax[tid * 4 + 1]),
                               fmaxf(pmax[tid * 4 + 2], pmax[tid * 4 + 3]));
            mnew = fmaxf(mold, mnew);
            sM[tid] = mnew;
            sA[tid] = __expf(mold - mnew);
        }
        __syncthreads();

        // Pass B: exponentiate, partial row sums
        {
            int r = tid >> 2, p = tid & 3;
            float mr = sM[r];
            float* row = sS + r * BN + p * 16;
            float sum = 0.f;
            #pragma unroll
            for (int c = 0; c < 16; c++) {
                float e = __expf(row[c] - mr);
                row[c] = e;
                sum += e;
            }
            psum[r * 4 + p] = sum;
        }
        __syncthreads();
        if (tid < BM) {
            sL[tid] = sL[tid] * sA[tid] +
                      (psum[tid * 4 + 0] + psum[tid * 4 + 1] +
                       psum[tid * 4 + 2] + psum[tid * 4 + 3]);
        }

        // Rescale accumulators by alpha
        #pragma unroll
        for (int i = 0; i < 8; i++) {
            float a = sA[ry * 8 + i];
            #pragma unroll
            for (int j = 0; j < 4; j++) acc[i][j] *= a;
        }

        // O += P @ V
        #pragma unroll 2
        for (int c = 0; c < BN; c++) {
            float4 vv = *(const float4*)(sV + c * DIM + cx * 4);
            #pragma unroll
            for (int i = 0; i < 8; i++) {
                float p = sS[(ry * 8 + i) * BN + c];
                acc[i][0] += p * vv.x;
                acc[i][1] += p * vv.y;
                acc[i][2] += p * vv.z;
                acc[i][3] += p * vv.w;
            }
        }
    }
    __syncthreads();  // sL final values visible to all threads

    float* obase = out + ((size_t)b * SEQ + qbase) * DIM;
    #pragma unroll
    for (int i = 0; i < 8; i++) {
        float inv = 1.0f / sL[ry * 8 + i];
        float4 o = make_float4(acc[i][0] * inv, acc[i][1] * inv,
                               acc[i][2] * inv, acc[i][3] * inv);
        *(float4*)(obase + (ry * 8 + i) * DIM + cx * 4) = o;
    }
}

// ---------------------------------------------------------------------------
extern "C" void kernel_launch(void* const* d_in, const int* in_sizes, int n_in,
                              void* d_out, int out_size) {
    const float* x  = (const float*)d_in[0];
    const float* Wk = (const float*)d_in[1];
    const float* Wq = (const float*)d_in[2];
    const float* Wv = (const float*)d_in[3];
    float* out = (float*)d_out;

    const size_t qkv_smem  = (size_t)(DIM * DIM + BM * DIM) * sizeof(float);        // 98304
    const size_t attn_smem = (size_t)(BM * DIM + DIM * BN + BN * DIM + BM * BN +
                                      3 * BM + 8 * BM) * sizeof(float);             // 117504

    cudaFuncSetAttribute(qkv_kernel,  cudaFuncAttributeMaxDynamicSharedMemorySize, (int)qkv_smem);
    cudaFuncSetAttribute(attn_kernel, cudaFuncAttributeMaxDynamicSharedMemorySize, (int)attn_smem);

    dim3 qkv_grid(NQT, BATCH, 3);
    qkv_kernel<<<qkv_grid, 256, qkv_smem>>>(x, Wk, Wq, Wv);

    attn_kernel<<<NQT * BATCH, 256, attn_smem>>>(out);
}